// round 2
// baseline (speedup 1.0000x reference)
#include <cuda_runtime.h>

#define BB 16
#define SS 2048
#define NC 8
#define NT 256
#define CHUNK (SS / NT)   // 8 events per thread
#define LOG2E 1.4426950408889634f
#define T1V 100.0f
#define EPSV 1e-8f

// Fast exp2 via MUFU (single EX2 instruction, no fast-math flag dependence).
__device__ __forceinline__ float ex2(float x) {
    float y;
    asm("ex2.approx.ftz.f32 %0, %1;" : "=f"(y) : "f"(x));
    return y;
}
// Fast log2 via MUFU; natural log = lg2 * ln2.
__device__ __forceinline__ float flog(float x) {
    float y;
    asm("lg2.approx.ftz.f32 %0, %1;" : "=f"(y) : "f"(x));
    return y * 0.6931471805599453f;
}

// Per-row partial results (deterministic; no atomics across blocks).
__device__ double g_partials[BB];

__global__ __launch_bounds__(NT)
void hawkes_row_kernel(const float* __restrict__ ts,
                       const int*   __restrict__ ms,
                       const float* __restrict__ mu,
                       const float* __restrict__ alphas,
                       const float* __restrict__ beta)
{
    __shared__ float  ts_sh[SS];
    __shared__ int    ms_sh[SS];
    __shared__ float  Vsh[NC][NT];   // scanned per-class chunk aggregates
    __shared__ float  Tsh[NT];       // chunk anchor timestamps
    __shared__ float  AB[NC * NC];   // alphas[m][c] * beta[c]
    __shared__ float  colsum[NC];    // sum_k alphas[k][c]
    __shared__ float  mu_s[NC];
    __shared__ double red[NT];

    const int b = blockIdx.x;
    const int t = threadIdx.x;

    // Stage the row into shared (coalesced).
    const float* tsr = ts + b * SS;
    const int*   msr = ms + b * SS;
    for (int i = t; i < SS; i += NT) {
        ts_sh[i] = tsr[i];
        ms_sh[i] = msr[i];
    }
    if (t < NC * NC) AB[t] = alphas[t] * beta[t & (NC - 1)];
    if (t < NC) {
        float s = 0.f;
        #pragma unroll
        for (int k = 0; k < NC; k++) s += alphas[k * NC + t];
        colsum[t] = s;
        mu_s[t]   = mu[t];
    }
    float bl2[NC];   // beta[c] * log2(e)  (so exp(-beta*x) = exp2(-bl2*x))
    #pragma unroll
    for (int c = 0; c < NC; c++) bl2[c] = beta[c] * LOG2E;
    __syncthreads();

    // ---------- Phase 1: per-chunk class sums anchored at chunk's last time ----------
    const int   base = t * CHUNK;
    const float Tt   = ts_sh[base + CHUNK - 1];
    float P[NC];
    #pragma unroll
    for (int c = 0; c < NC; c++) P[c] = 0.f;
    #pragma unroll
    for (int j = 0; j < CHUNK; j++) {
        float tj = ts_sh[base + j];
        int   m  = ms_sh[base + j];
        if (tj > 0.f) P[m] += ex2(bl2[m] * (tj - Tt));   // exponent <= 0
    }
    #pragma unroll
    for (int c = 0; c < NC; c++) Vsh[c][t] = P[c];
    Tsh[t] = Tt;
    __syncthreads();

    // ---------- Phase 2: Kogge-Stone inclusive scan over chunks ----------
    // Invariant: Vsh[c][t] = sum over covered chunks of P decayed to anchor Tt.
    for (int off = 1; off < NT; off <<= 1) {
        float pv[NC];
        float Tp = 0.f;
        const bool has = (t >= off);
        if (has) {
            Tp = Tsh[t - off];
            #pragma unroll
            for (int c = 0; c < NC; c++) pv[c] = Vsh[c][t - off];
        }
        __syncthreads();
        if (has) {
            #pragma unroll
            for (int c = 0; c < NC; c++)
                Vsh[c][t] += ex2(bl2[c] * (Tp - Tt)) * pv[c];  // Tp <= Tt
        }
        __syncthreads();
    }

    // ---------- Phase 3: sequential replay within chunk ----------
    float L[NC];
    float tprev;
    if (t == 0) {
        #pragma unroll
        for (int c = 0; c < NC; c++) L[c] = 0.f;
        tprev = ts_sh[0];
    } else {
        tprev = Tsh[t - 1];
        #pragma unroll
        for (int c = 0; c < NC; c++) L[c] = Vsh[c][t - 1];  // exclusive prefix
    }

    double acc = 0.0;   // sumlog - integ contribution for this thread
    #pragma unroll
    for (int j = 0; j < CHUNK; j++) {
        const int   i  = base + j;
        const float ti = ts_sh[i];
        const int   m  = ms_sh[i];
        const float dt = ti - tprev;
        tprev = ti;

        float lam = mu_s[m];
        #pragma unroll
        for (int c = 0; c < NC; c++) {
            L[c] *= ex2(-bl2[c] * dt);
            lam  += AB[m * NC + c] * L[c];
        }
        if (ti > 0.f) {
            float contrib = flog(lam + EPSV)
                          - colsum[m] * (1.f - ex2(-bl2[m] * (T1V - ti)));
            acc += (double)contrib;
            L[m] += 1.f;   // event i becomes a source for later events
        }
    }

    // ---------- Block reduction (double) ----------
    red[t] = acc;
    __syncthreads();
    for (int s = NT / 2; s > 0; s >>= 1) {
        if (t < s) red[t] += red[t + s];
        __syncthreads();
    }
    if (t == 0) g_partials[b] = red[0];
}

__global__ void hawkes_final_kernel(const float* __restrict__ mu, float* __restrict__ out)
{
    if (threadIdx.x == 0) {
        double s = 0.0;
        #pragma unroll
        for (int i = 0; i < BB; i++) s += g_partials[i];
        double musum = 0.0;
        #pragma unroll
        for (int c = 0; c < NC; c++) musum += (double)mu[c];
        out[0] = (float)(s - musum * (double)T1V);
    }
}

extern "C" void kernel_launch(void* const* d_in, const int* in_sizes, int n_in,
                              void* d_out, int out_size)
{
    const float* ts     = (const float*)d_in[0];
    const int*   ms     = (const int*)  d_in[1];
    const float* mu     = (const float*)d_in[2];
    const float* alphas = (const float*)d_in[3];
    const float* beta   = (const float*)d_in[4];
    float*       out    = (float*)d_out;

    hawkes_row_kernel<<<BB, NT>>>(ts, ms, mu, alphas, beta);
    hawkes_final_kernel<<<1, 32>>>(mu, out);
}

// round 3
// speedup vs baseline: 1.1292x; 1.1292x over previous
#include <cuda_runtime.h>

#define BB 16
#define SS 2048
#define NC 8
#define NT 256
#define CHUNK 8            // SS / NT
#define LOG2E 1.4426950408889634f
#define T1V 100.0f
#define EPSV 1e-8f

// Fast exp2/log via MUFU (single EX2/LG2 instruction).
__device__ __forceinline__ float ex2(float x) {
    float y; asm("ex2.approx.ftz.f32 %0, %1;" : "=f"(y) : "f"(x)); return y;
}
__device__ __forceinline__ float flog(float x) {
    float y; asm("lg2.approx.ftz.f32 %0, %1;" : "=f"(y) : "f"(x));
    return y * 0.6931471805599453f;
}

// Cross-block communication (no allocations allowed).
__device__ double       g_partials[BB];
__device__ unsigned int g_ticket;      // zero-init; last block resets to 0 each run

__global__ __launch_bounds__(NT)
void hawkes_fused_kernel(const float* __restrict__ ts,
                         const int*   __restrict__ ms,
                         const float* __restrict__ mu,
                         const float* __restrict__ alphas,
                         const float* __restrict__ beta,
                         float*       __restrict__ out)
{
    __shared__ alignas(16) float ts_sh[SS];
    __shared__ alignas(16) int   ms_sh[SS];
    __shared__ float V0[NC][NT];     // scan ping
    __shared__ float V1[NC][NT];     // scan pong
    __shared__ float Tsh[NT];        // chunk anchor timestamps
    __shared__ float AB[NC * NC];    // alphas[m][c] * beta[c]
    __shared__ float colsum[NC];     // sum_k alphas[k][c]
    __shared__ float mu_s[NC];
    __shared__ double wred[NT / 32];

    const int b = blockIdx.x;
    const int t = threadIdx.x;

    // ---- Stage the row into shared (vectorized, coalesced) ----
    {
        const float4* ts4 = (const float4*)(ts + b * SS);
        const int4*   ms4 = (const int4*)(ms + b * SS);
        float4* tss = (float4*)ts_sh;
        int4*   mss = (int4*)ms_sh;
        #pragma unroll
        for (int i = t; i < SS / 4; i += NT) { tss[i] = ts4[i]; mss[i] = ms4[i]; }
    }
    if (t < NC * NC) AB[t] = alphas[t] * beta[t & (NC - 1)];
    if (t < NC) {
        float s = 0.f;
        #pragma unroll
        for (int k = 0; k < NC; k++) s += alphas[k * NC + t];
        colsum[t] = s;
        mu_s[t]   = mu[t];
    }
    float bl2[NC];   // beta[c]*log2(e):  exp(-beta*x) == exp2(-bl2*x)
    #pragma unroll
    for (int c = 0; c < NC; c++) bl2[c] = beta[c] * LOG2E;
    __syncthreads();

    // ---- Load this thread's chunk into registers (LDS.128, conflict-free) ----
    const int base = t * CHUNK;
    float tloc[CHUNK];
    int   mloc[CHUNK];
    *(float4*)&tloc[0] = ((float4*)ts_sh)[t * 2];
    *(float4*)&tloc[4] = ((float4*)ts_sh)[t * 2 + 1];
    *(int4*)&mloc[0]   = ((int4*)ms_sh)[t * 2];
    *(int4*)&mloc[4]   = ((int4*)ms_sh)[t * 2 + 1];
    (void)base;

    // ---- Phase 1: per-chunk class sums anchored at chunk's last timestamp ----
    const float Tt = tloc[CHUNK - 1];
    float P[NC];
    #pragma unroll
    for (int c = 0; c < NC; c++) P[c] = 0.f;
    #pragma unroll
    for (int j = 0; j < CHUNK; j++) {
        float tj = tloc[j];
        int   m  = mloc[j];
        if (tj > 0.f) P[m] += ex2(bl2[m] * (tj - Tt));   // exponent <= 0
    }
    #pragma unroll
    for (int c = 0; c < NC; c++) V0[c][t] = P[c];
    Tsh[t] = Tt;
    __syncthreads();

    // ---- Phase 2: Kogge-Stone scan, double-buffered (1 barrier/step) ----
    float (*cur)[NT] = V0;
    float (*nxt)[NT] = V1;
    #pragma unroll
    for (int off = 1; off < NT; off <<= 1) {
        const bool has = (t >= off);
        float Tp = has ? Tsh[t - off] : 0.f;
        float dec[NC];
        #pragma unroll
        for (int c = 0; c < NC; c++)
            dec[c] = has ? ex2(bl2[c] * (Tp - Tt)) : 0.f;   // Tp <= Tt
        #pragma unroll
        for (int c = 0; c < NC; c++) {
            float v = cur[c][t];
            if (has) v += dec[c] * cur[c][t - off];
            nxt[c][t] = v;
        }
        __syncthreads();
        float (*tmp)[NT] = cur; cur = nxt; nxt = tmp;
    }

    // ---- Phase 3: sequential replay within chunk (exclusive prefix state) ----
    float L[NC];
    float tprev;
    if (t == 0) {
        #pragma unroll
        for (int c = 0; c < NC; c++) L[c] = 0.f;
        tprev = tloc[0];
    } else {
        tprev = Tsh[t - 1];
        #pragma unroll
        for (int c = 0; c < NC; c++) L[c] = cur[c][t - 1];
    }

    double acc = 0.0;   // this thread's (sumlog - integ) contribution
    #pragma unroll
    for (int j = 0; j < CHUNK; j++) {
        const float ti = tloc[j];
        const int   m  = mloc[j];
        const float dt = ti - tprev;
        tprev = ti;

        float lam = mu_s[m];
        #pragma unroll
        for (int c = 0; c < NC; c++) {
            L[c] *= ex2(-bl2[c] * dt);
            lam  += AB[m * NC + c] * L[c];
        }
        if (ti > 0.f) {
            float contrib = flog(lam + EPSV)
                          - colsum[m] * (1.f - ex2(-bl2[m] * (T1V - ti)));
            acc += (double)contrib;
            L[m] += 1.f;
        }
    }

    // ---- Block reduction: warp shuffles + one barrier ----
    #pragma unroll
    for (int off = 16; off > 0; off >>= 1)
        acc += __shfl_down_sync(0xffffffffu, acc, off);
    if ((t & 31) == 0) wred[t >> 5] = acc;
    __syncthreads();

    // ---- Fused finalization: fence + ticket; last block sums in fixed order ----
    if (t == 0) {
        double s = 0.0;
        #pragma unroll
        for (int w = 0; w < NT / 32; w++) s += wred[w];
        g_partials[b] = s;
        __threadfence();
        unsigned tk = atomicAdd(&g_ticket, 1u);
        if (tk == BB - 1) {             // last block to arrive finalizes
            __threadfence();
            double tot = 0.0;
            #pragma unroll
            for (int i = 0; i < BB; i++) tot += __ldcg(&g_partials[i]);
            double musum = 0.0;
            #pragma unroll
            for (int c = 0; c < NC; c++) musum += (double)mu_s[c];
            out[0] = (float)(tot - musum * (double)T1V);
            __threadfence();
            g_ticket = 0;               // reset for next graph replay
        }
    }
}

extern "C" void kernel_launch(void* const* d_in, const int* in_sizes, int n_in,
                              void* d_out, int out_size)
{
    const float* ts     = (const float*)d_in[0];
    const int*   ms     = (const int*)  d_in[1];
    const float* mu     = (const float*)d_in[2];
    const float* alphas = (const float*)d_in[3];
    const float* beta   = (const float*)d_in[4];
    float*       out    = (float*)d_out;

    hawkes_fused_kernel<<<BB, NT>>>(ts, ms, mu, alphas, beta, out);
}